// round 5
// baseline (speedup 1.0000x reference)
#include <cuda_runtime.h>
#include <cstdint>

// ---------------------------------------------------------------------------
// PureCartesianTensorProductO3.
// R5: 256 threads = 2 groups of 128. Group g handles parity combos with equal
// s_out (g0: ss{0,3}, g1: ss{1,2}) -> disjoint output regions, accumulators
// persist across the group's two combos. a-chunk halved to 2 so per-group
// B/W staging buffers fit: smem 193KB, 1 CTA/SM, 2 warps/SMSP (was 1).
// ---------------------------------------------------------------------------

#define NROWS   8192
#define FEAT    832
#define SBLK    416
#define TILE    16
#define NTHREADS 256
#define CHUNK   2
#define KSLOTS  (CHUNK * 32)      // 64 k-slots per staged chunk

// path tables (compile-time)
__host__ __device__ constexpr int kP3[3]   = {1, 3, 9};
__host__ __device__ constexpr int kLOFF[3] = {0, 32, 128};
__host__ __device__ constexpr int kL1[15] = {0,0,0,1,1,1,1,1,1,2,2,2,2,2,2};
__host__ __device__ constexpr int kL2[15] = {0,1,2,0,1,1,1,2,2,0,1,1,2,2,2};
__host__ __device__ constexpr int kLO[15] = {0,1,2,1,2,0,1,1,2,2,1,2,2,0,1};
__host__ __device__ constexpr int kUE[15] = {0,0,0,0,0,0,1,0,1,0,0,1,0,0,1};

// SMEM carve (floats)
#define SX_STRIDE 832                          // unpadded; slot-fast staging is conflict-free
#define SX_FLOATS (TILE * SX_STRIDE)           // 13312
#define SB_G      (KSLOTS * 9 * TILE)          // 9216 per group (max Mout=9)
#define SW_STRIDE 34
#define SW_G      (KSLOTS * SW_STRIDE)         // 2176 per group
#define SMEM_FLOATS (2 * SX_FLOATS + 2 * SB_G + 2 * SW_G)   // 49408
#define SMEM_BYTES (SMEM_FLOATS * 4)           // 197632 B

typedef unsigned long long u64;

__device__ __forceinline__ u64 pk2(float x, float y) {
    u64 r; asm("mov.b64 %0, {%1, %2};" : "=l"(r) : "f"(x), "f"(y)); return r;
}
__device__ __forceinline__ void upk2(u64 v, float& x, float& y) {
    asm("mov.b64 {%0, %1}, %2;" : "=f"(x), "=f"(y) : "l"(v));
}
// packed 2x fp32 FMA (PTX-only on sm_103a)
__device__ __forceinline__ void ffma2(u64& d, u64 a, u64 b) {
    asm("fma.rn.f32x2 %0, %1, %2, %0;" : "+l"(d) : "l"(a), "l"(b));
}

__device__ __forceinline__ float dot3(const float* __restrict__ u, const float* __restrict__ v) {
    return fmaf(u[0], v[0], fmaf(u[1], v[1], u[2] * v[2]));
}
__device__ __forceinline__ void cross3(const float* __restrict__ u, const float* __restrict__ v,
                                       float* __restrict__ o) {
    o[0] = u[1] * v[2] - u[2] * v[1];
    o[1] = u[2] * v[0] - u[0] * v[2];
    o[2] = u[0] * v[1] - u[1] * v[0];
}

// Spatial contraction per path (verified against _path_eq in R1 post-mortem)
template <int P>
__device__ __forceinline__ void compute_B(const float* __restrict__ t1,
                                          const float* __restrict__ t2,
                                          float* __restrict__ B) {
    if constexpr (P == 0) {
        B[0] = t1[0] * t2[0];
    } else if constexpr (P == 1) {
        #pragma unroll
        for (int m = 0; m < 3; ++m) B[m] = t1[0] * t2[m];
    } else if constexpr (P == 2) {
        #pragma unroll
        for (int m = 0; m < 9; ++m) B[m] = t1[0] * t2[m];
    } else if constexpr (P == 3) {
        #pragma unroll
        for (int m = 0; m < 3; ++m) B[m] = t1[m] * t2[0];
    } else if constexpr (P == 4) {
        #pragma unroll
        for (int i = 0; i < 3; ++i)
            #pragma unroll
            for (int j = 0; j < 3; ++j) B[3 * i + j] = t1[i] * t2[j];
    } else if constexpr (P == 5) {
        B[0] = dot3(t1, t2);
    } else if constexpr (P == 6) {
        cross3(t1, t2, B);
    } else if constexpr (P == 7) {
        #pragma unroll
        for (int d = 0; d < 3; ++d) B[d] = dot3(t1, t2 + 3 * d);
    } else if constexpr (P == 8) {
        #pragma unroll
        for (int d = 0; d < 3; ++d) cross3(t1, t2 + 3 * d, B + 3 * d);
    } else if constexpr (P == 9) {
        #pragma unroll
        for (int m = 0; m < 9; ++m) B[m] = t1[m] * t2[0];
    } else if constexpr (P == 10) {
        #pragma unroll
        for (int c = 0; c < 3; ++c) B[c] = dot3(t1 + 3 * c, t2);
    } else if constexpr (P == 11) {
        #pragma unroll
        for (int c = 0; c < 3; ++c) cross3(t1 + 3 * c, t2, B + 3 * c);
    } else if constexpr (P == 12) {
        #pragma unroll
        for (int c = 0; c < 3; ++c)
            #pragma unroll
            for (int e = 0; e < 3; ++e) B[3 * c + e] = dot3(t1 + 3 * c, t2 + 3 * e);
    } else if constexpr (P == 13) {
        float s = 0.f;
        #pragma unroll
        for (int i = 0; i < 9; ++i) s = fmaf(t1[i], t2[i], s);
        B[0] = s;
    } else {  // P==14
        float M01 = dot3(t1 + 0, t2 + 3), M02 = dot3(t1 + 0, t2 + 6);
        float M10 = dot3(t1 + 3, t2 + 0), M12 = dot3(t1 + 3, t2 + 6);
        float M20 = dot3(t1 + 6, t2 + 0), M21 = dot3(t1 + 6, t2 + 3);
        B[0] = M12 - M21;
        B[1] = M20 - M02;
        B[2] = M01 - M10;
    }
}

template <int P>
__device__ __forceinline__ void process_path(const float* __restrict__ wgt,
                                             float* __restrict__ out,
                                             const float* __restrict__ sx1,
                                             const float* __restrict__ sx2,
                                             float* __restrict__ sB,   // group's buffer
                                             float* __restrict__ sW,   // group's buffer
                                             int row0, int wtid, int group) {
    constexpr int L1 = kL1[P], L2 = kL2[P], Lo = kLO[P], UE = kUE[P];
    constexpr int d1 = kP3[L1], d2 = kP3[L2], Mout = kP3[Lo];
    constexpr int O1 = kLOFF[L1], O2 = kLOFF[L2], Oo = kLOFF[Lo];

    const int zp = wtid & 15;   // Z-pair: Z = 2*zp, 2*zp+1
    const int rp = wtid >> 4;   // row-pair: rows 2*rp, 2*rp+1  (rp in [0,8))

    // group0 handles ss {0,3} (s_out = UE), group1 handles ss {1,2} (s_out = 1^UE)
    const int so = (group ^ UE) & 1 ? 1 ^ 0 : 0;  // placeholder, fixed below
    const int s_out = group == 0 ? UE : (1 ^ UE);
    (void)so;

    u64 acc0[Mout], acc1[Mout];
    #pragma unroll
    for (int m = 0; m < Mout; ++m) { acc0[m] = 0ull; acc1[m] = 0ull; }

    #pragma unroll 1
    for (int ssi = 0; ssi < 2; ++ssi) {
        const int ss = (group == 0) ? (ssi == 0 ? 0 : 3) : (ssi == 0 ? 1 : 2);
        const int s1 = ss >> 1, s2 = ss & 1;
        const float* wb = wgt + (size_t)(P * 4 + ss) * 32768;

        #pragma unroll 1
        for (int a0 = 0; a0 < 32; a0 += CHUNK) {
            __syncthreads();  // previous GEMM done reading sB/sW (also orders x-fill)
            // ---- stage W slice: 32Z x 64 (rem = ac*32+b) per group; 16 iters
            #pragma unroll
            for (int it = 0; it < 32 * KSLOTS / 128; ++it) {
                int i = wtid + it * 128;
                int Z = i >> 6, rem = i & (KSLOTS - 1);
                sW[rem * SW_STRIDE + Z] = wb[Z * 1024 + a0 * 32 + rem];
            }
            // ---- stage B: 64 slots x 16 rows, slot-fast decode (conflict-free on
            //      unpadded sx since gcd(d2,32)=1; t1 broadcast within 32 lanes)
            #pragma unroll
            for (int it = 0; it < KSLOTS * TILE / 128; ++it) {
                int e = wtid + it * 128;
                int slot = e & (KSLOTS - 1), r = e >> 6;
                int ac = slot >> 5, b = slot & 31;
                const float* t1 = sx1 + r * SX_STRIDE + s1 * SBLK + O1 + (a0 + ac) * d1;
                const float* t2 = sx2 + r * SX_STRIDE + s2 * SBLK + O2 + b * d2;
                float Bm[Mout];
                compute_B<P>(t1, t2, Bm);
                #pragma unroll
                for (int m = 0; m < Mout; ++m) sB[(slot * Mout + m) * TILE + r] = Bm[m];
            }
            __syncthreads();
            // ---- rank-64 update, packed f32x2 over the row pair
            #pragma unroll 4
            for (int k = 0; k < KSLOTS; ++k) {
                float2 w2 = *reinterpret_cast<const float2*>(sW + k * SW_STRIDE + 2 * zp);
                u64 wA = pk2(w2.x, w2.x);  // Z = 2*zp
                u64 wB = pk2(w2.y, w2.y);  // Z = 2*zp+1
                const float* bp = sB + (size_t)k * Mout * TILE + 2 * rp;
                #pragma unroll
                for (int m = 0; m < Mout; ++m) {
                    u64 bv = *reinterpret_cast<const u64*>(bp + m * TILE);
                    ffma2(acc0[m], wA, bv);
                    ffma2(acc1[m], wB, bv);
                }
            }
        }
    }
    // ---- flush once per path per group (groups target disjoint s_out blocks)
    const int ob = s_out * SBLK + Oo;
    float* o0 = out + (size_t)(row0 + 2 * rp) * FEAT;
    float* o1 = o0 + FEAT;
    #pragma unroll
    for (int m = 0; m < Mout; ++m) {
        float v00, v01, v10, v11;
        upk2(acc0[m], v00, v01);
        upk2(acc1[m], v10, v11);
        o0[ob + (2 * zp) * Mout + m]     += v00;
        o1[ob + (2 * zp) * Mout + m]     += v01;
        o0[ob + (2 * zp + 1) * Mout + m] += v10;
        o1[ob + (2 * zp + 1) * Mout + m] += v11;
    }
}

__global__ __launch_bounds__(NTHREADS)
void tp_o3_kernel(const float* __restrict__ x1, const float* __restrict__ x2,
                  const float* __restrict__ wgt, float* __restrict__ out) {
    extern __shared__ float sm[];
    float* sx1 = sm;
    float* sx2 = sx1 + SX_FLOATS;
    float* sBb = sx2 + SX_FLOATS;
    float* sWb = sBb + 2 * SB_G;

    const int tid   = threadIdx.x;
    const int group = tid >> 7;
    const int wtid  = tid & 127;
    const int row0  = blockIdx.x * TILE;

    float* sB = sBb + group * SB_G;
    float* sW = sWb + group * SW_G;

    // stage input tiles (contiguous copy; stride 832 is 16B-aligned per row)
    {
        const float4* g1 = reinterpret_cast<const float4*>(x1 + (size_t)row0 * FEAT);
        const float4* g2 = reinterpret_cast<const float4*>(x2 + (size_t)row0 * FEAT);
        float4* s1v = reinterpret_cast<float4*>(sx1);
        float4* s2v = reinterpret_cast<float4*>(sx2);
        #pragma unroll 4
        for (int i = tid; i < TILE * FEAT / 4; i += NTHREADS) {
            s1v[i] = g1[i];
            s2v[i] = g2[i];
        }
    }
    // (first __syncthreads inside each chunk loop orders the fill)

    process_path<0>(wgt, out, sx1, sx2, sB, sW, row0, wtid, group);
    process_path<1>(wgt, out, sx1, sx2, sB, sW, row0, wtid, group);
    process_path<2>(wgt, out, sx1, sx2, sB, sW, row0, wtid, group);
    process_path<3>(wgt, out, sx1, sx2, sB, sW, row0, wtid, group);
    process_path<4>(wgt, out, sx1, sx2, sB, sW, row0, wtid, group);
    process_path<5>(wgt, out, sx1, sx2, sB, sW, row0, wtid, group);
    process_path<6>(wgt, out, sx1, sx2, sB, sW, row0, wtid, group);
    process_path<7>(wgt, out, sx1, sx2, sB, sW, row0, wtid, group);
    process_path<8>(wgt, out, sx1, sx2, sB, sW, row0, wtid, group);
    process_path<9>(wgt, out, sx1, sx2, sB, sW, row0, wtid, group);
    process_path<10>(wgt, out, sx1, sx2, sB, sW, row0, wtid, group);
    process_path<11>(wgt, out, sx1, sx2, sB, sW, row0, wtid, group);
    process_path<12>(wgt, out, sx1, sx2, sB, sW, row0, wtid, group);
    process_path<13>(wgt, out, sx1, sx2, sB, sW, row0, wtid, group);
    process_path<14>(wgt, out, sx1, sx2, sB, sW, row0, wtid, group);
}

extern "C" void kernel_launch(void* const* d_in, const int* in_sizes, int n_in,
                              void* d_out, int out_size) {
    const float* x1  = (const float*)d_in[0];
    const float* x2  = (const float*)d_in[1];
    const float* wgt = (const float*)d_in[2];
    float* out = (float*)d_out;

    cudaFuncSetAttribute(tp_o3_kernel, cudaFuncAttributeMaxDynamicSharedMemorySize, SMEM_BYTES);
    cudaMemsetAsync(d_out, 0, (size_t)out_size * sizeof(float), 0);
    tp_o3_kernel<<<NROWS / TILE, NTHREADS, SMEM_BYTES>>>(x1, x2, wgt, out);
}

// round 6
// speedup vs baseline: 1.3871x; 1.3871x over previous
#include <cuda_runtime.h>
#include <cstdint>

// ---------------------------------------------------------------------------
// PureCartesianTensorProductO3.
// R6: R4 schedule (128 thr, 16-row tile, CHUNK=4) + vectorized m-pair B loads
// (LDS.128 -> two f32x2 operands, no packing movs) + launch_bounds(128,1).
// ---------------------------------------------------------------------------

#define NROWS   8192
#define FEAT    832
#define SBLK    416
#define TILE    16
#define NTHREADS 128
#define KSLOTS  128

// path tables (compile-time)
__host__ __device__ constexpr int kP3[3]   = {1, 3, 9};
__host__ __device__ constexpr int kLOFF[3] = {0, 32, 128};
__host__ __device__ constexpr int kL1[15] = {0,0,0,1,1,1,1,1,1,2,2,2,2,2,2};
__host__ __device__ constexpr int kL2[15] = {0,1,2,0,1,1,1,2,2,0,1,1,2,2,2};
__host__ __device__ constexpr int kLO[15] = {0,1,2,1,2,0,1,1,2,2,1,2,2,0,1};
__host__ __device__ constexpr int kUE[15] = {0,0,0,0,0,0,1,0,1,0,0,1,0,0,1};

// SMEM carve (floats)
#define SX_STRIDE 833
#define SX_FLOATS (TILE * SX_STRIDE)          // 13328
#define SB_FLOATS (KSLOTS * 160)              // 20480 (Mout=9 layout is largest)
#define SW_STRIDE 34
#define SW_FLOATS (KSLOTS * SW_STRIDE)        // 4352
#define SMEM_FLOATS (2 * SX_FLOATS + SB_FLOATS + SW_FLOATS)   // 51488
#define SMEM_BYTES (SMEM_FLOATS * 4)          // 205952 B

typedef unsigned long long u64;

__device__ __forceinline__ u64 pk2(float x, float y) {
    u64 r; asm("mov.b64 %0, {%1, %2};" : "=l"(r) : "f"(x), "f"(y)); return r;
}
__device__ __forceinline__ void upk2(u64 v, float& x, float& y) {
    asm("mov.b64 {%0, %1}, %2;" : "=f"(x), "=f"(y) : "l"(v));
}
// packed 2x fp32 FMA (PTX-only on sm_103a)
__device__ __forceinline__ void ffma2(u64& d, u64 a, u64 b) {
    asm("fma.rn.f32x2 %0, %1, %2, %0;" : "+l"(d) : "l"(a), "l"(b));
}

__device__ __forceinline__ float dot3(const float* __restrict__ u, const float* __restrict__ v) {
    return fmaf(u[0], v[0], fmaf(u[1], v[1], u[2] * v[2]));
}
__device__ __forceinline__ void cross3(const float* __restrict__ u, const float* __restrict__ v,
                                       float* __restrict__ o) {
    o[0] = u[1] * v[2] - u[2] * v[1];
    o[1] = u[2] * v[0] - u[0] * v[2];
    o[2] = u[0] * v[1] - u[1] * v[0];
}

// Spatial contraction per path (verified against _path_eq; unchanged since R1 fix)
template <int P>
__device__ __forceinline__ void compute_B(const float* __restrict__ t1,
                                          const float* __restrict__ t2,
                                          float* __restrict__ B) {
    if constexpr (P == 0) {
        B[0] = t1[0] * t2[0];
    } else if constexpr (P == 1) {
        #pragma unroll
        for (int m = 0; m < 3; ++m) B[m] = t1[0] * t2[m];
    } else if constexpr (P == 2) {
        #pragma unroll
        for (int m = 0; m < 9; ++m) B[m] = t1[0] * t2[m];
    } else if constexpr (P == 3) {
        #pragma unroll
        for (int m = 0; m < 3; ++m) B[m] = t1[m] * t2[0];
    } else if constexpr (P == 4) {
        #pragma unroll
        for (int i = 0; i < 3; ++i)
            #pragma unroll
            for (int j = 0; j < 3; ++j) B[3 * i + j] = t1[i] * t2[j];
    } else if constexpr (P == 5) {
        B[0] = dot3(t1, t2);
    } else if constexpr (P == 6) {
        cross3(t1, t2, B);
    } else if constexpr (P == 7) {
        #pragma unroll
        for (int d = 0; d < 3; ++d) B[d] = dot3(t1, t2 + 3 * d);
    } else if constexpr (P == 8) {
        #pragma unroll
        for (int d = 0; d < 3; ++d) cross3(t1, t2 + 3 * d, B + 3 * d);
    } else if constexpr (P == 9) {
        #pragma unroll
        for (int m = 0; m < 9; ++m) B[m] = t1[m] * t2[0];
    } else if constexpr (P == 10) {
        #pragma unroll
        for (int c = 0; c < 3; ++c) B[c] = dot3(t1 + 3 * c, t2);
    } else if constexpr (P == 11) {
        #pragma unroll
        for (int c = 0; c < 3; ++c) cross3(t1 + 3 * c, t2, B + 3 * c);
    } else if constexpr (P == 12) {
        #pragma unroll
        for (int c = 0; c < 3; ++c)
            #pragma unroll
            for (int e = 0; e < 3; ++e) B[3 * c + e] = dot3(t1 + 3 * c, t2 + 3 * e);
    } else if constexpr (P == 13) {
        float s = 0.f;
        #pragma unroll
        for (int i = 0; i < 9; ++i) s = fmaf(t1[i], t2[i], s);
        B[0] = s;
    } else {  // P==14
        float M01 = dot3(t1 + 0, t2 + 3), M02 = dot3(t1 + 0, t2 + 6);
        float M10 = dot3(t1 + 3, t2 + 0), M12 = dot3(t1 + 3, t2 + 6);
        float M20 = dot3(t1 + 6, t2 + 0), M21 = dot3(t1 + 6, t2 + 3);
        B[0] = M12 - M21;
        B[1] = M20 - M02;
        B[2] = M01 - M10;
    }
}

// sB layouts by Mout:
//   Mout==9: [k][rp][m*2+p]   rp-stride 20, k-stride 160  (LDS.128 pairs, 16B aligned)
//   Mout==3: [k][rp][m*2+p]   rp-stride  8, k-stride  64  (1x LDS.128 + 1x LDS.64)
//   Mout==1: [k][r]           k-stride 16                 (LDS.64 row-pair)
template <int Mout> struct BLay;
template <> struct BLay<9> { static const int RPS = 20, KS = 160; };
template <> struct BLay<3> { static const int RPS = 8,  KS = 64;  };
template <> struct BLay<1> { static const int RPS = 0,  KS = 16;  };

template <int P>
__device__ __forceinline__ void process_path(const float* __restrict__ wgt,
                                             float* __restrict__ out,
                                             const float* __restrict__ sx1,
                                             const float* __restrict__ sx2,
                                             float* __restrict__ sB,
                                             float* __restrict__ sW,
                                             int row0, int tid) {
    constexpr int L1 = kL1[P], L2 = kL2[P], Lo = kLO[P], UE = kUE[P];
    constexpr int d1 = kP3[L1], d2 = kP3[L2], Mout = kP3[Lo];
    constexpr int O1 = kLOFF[L1], O2 = kLOFF[L2], Oo = kLOFF[Lo];
    constexpr int RPS = BLay<Mout>::RPS, KS = BLay<Mout>::KS;

    const int zp = tid & 15;   // Z-pair: Z = 2*zp, 2*zp+1
    const int rp = tid >> 4;   // row-pair: rows 2*rp, 2*rp+1  (rp in [0,8))

    #pragma unroll 1
    for (int ss = 0; ss < 4; ++ss) {
        const int s1 = ss >> 1, s2 = ss & 1;
        const int so = s1 ^ s2 ^ UE;
        const float* wb = wgt + (size_t)(P * 4 + ss) * 32768;

        u64 acc0[Mout], acc1[Mout];
        #pragma unroll
        for (int m = 0; m < Mout; ++m) { acc0[m] = 0ull; acc1[m] = 0ull; }

        #pragma unroll 1
        for (int a0 = 0; a0 < 32; a0 += 4) {
            __syncthreads();  // previous GEMM done reading sB/sW (also orders x fill)
            // ---- stage W slice: W[Z, a0 + (k>>5), k&31] -> sW[k*34 + Z]
            #pragma unroll
            for (int it = 0; it < 32; ++it) {
                int i = tid + it * NTHREADS;
                int Z = i >> 7, k = i & 127;
                sW[k * SW_STRIDE + Z] = wb[Z * 1024 + a0 * 32 + k];
            }
            // ---- stage B (k = ac*32 + b), slot-slow decode as in R4
            #pragma unroll
            for (int it = 0; it < 16; ++it) {
                int e = tid + it * NTHREADS;
                int r = e & 15, k = e >> 4;          // k in [0,128)
                int ac = k >> 5, b = k & 31;
                const float* t1 = sx1 + r * SX_STRIDE + s1 * SBLK + O1 + (a0 + ac) * d1;
                const float* t2 = sx2 + r * SX_STRIDE + s2 * SBLK + O2 + b * d2;
                float Bm[Mout];
                compute_B<P>(t1, t2, Bm);
                if constexpr (Mout == 1) {
                    sB[k * KS + r] = Bm[0];
                } else {
                    float* d = sB + k * KS + (r >> 1) * RPS + (r & 1);
                    #pragma unroll
                    for (int m = 0; m < Mout; ++m) d[2 * m] = Bm[m];
                }
            }
            __syncthreads();
            // ---- rank-128 update, f32x2 over the row pair
            #pragma unroll 4
            for (int k = 0; k < KSLOTS; ++k) {
                float2 w2 = *reinterpret_cast<const float2*>(sW + k * SW_STRIDE + 2 * zp);
                u64 wA = pk2(w2.x, w2.x);  // Z = 2*zp
                u64 wB = pk2(w2.y, w2.y);  // Z = 2*zp+1
                if constexpr (Mout == 9) {
                    const float* bp = sB + k * KS + rp * RPS;
                    ulonglong2 q0 = *reinterpret_cast<const ulonglong2*>(bp);       // m0,m1
                    ulonglong2 q1 = *reinterpret_cast<const ulonglong2*>(bp + 4);   // m2,m3
                    ulonglong2 q2 = *reinterpret_cast<const ulonglong2*>(bp + 8);   // m4,m5
                    ulonglong2 q3 = *reinterpret_cast<const ulonglong2*>(bp + 12);  // m6,m7
                    u64 q4 = *reinterpret_cast<const u64*>(bp + 16);                // m8
                    ffma2(acc0[0], wA, q0.x); ffma2(acc1[0], wB, q0.x);
                    ffma2(acc0[1], wA, q0.y); ffma2(acc1[1], wB, q0.y);
                    ffma2(acc0[2], wA, q1.x); ffma2(acc1[2], wB, q1.x);
                    ffma2(acc0[3], wA, q1.y); ffma2(acc1[3], wB, q1.y);
                    ffma2(acc0[4], wA, q2.x); ffma2(acc1[4], wB, q2.x);
                    ffma2(acc0[5], wA, q2.y); ffma2(acc1[5], wB, q2.y);
                    ffma2(acc0[6], wA, q3.x); ffma2(acc1[6], wB, q3.x);
                    ffma2(acc0[7], wA, q3.y); ffma2(acc1[7], wB, q3.y);
                    ffma2(acc0[8], wA, q4);   ffma2(acc1[8], wB, q4);
                } else if constexpr (Mout == 3) {
                    const float* bp = sB + k * KS + rp * RPS;
                    ulonglong2 q0 = *reinterpret_cast<const ulonglong2*>(bp);       // m0,m1
                    u64 q1 = *reinterpret_cast<const u64*>(bp + 4);                 // m2
                    ffma2(acc0[0], wA, q0.x); ffma2(acc1[0], wB, q0.x);
                    ffma2(acc0[1], wA, q0.y); ffma2(acc1[1], wB, q0.y);
                    ffma2(acc0[2], wA, q1);   ffma2(acc1[2], wB, q1);
                } else {
                    u64 bv = *reinterpret_cast<const u64*>(sB + k * KS + 2 * rp);
                    ffma2(acc0[0], wA, bv);
                    ffma2(acc1[0], wB, bv);
                }
            }
        }
        // ---- flush (rows exclusive per block; locations exclusive per thread)
        const int ob = so * SBLK + Oo;
        float* o0 = out + (size_t)(row0 + 2 * rp) * FEAT;
        float* o1 = o0 + FEAT;
        #pragma unroll
        for (int m = 0; m < Mout; ++m) {
            float v00, v01, v10, v11;
            upk2(acc0[m], v00, v01);
            upk2(acc1[m], v10, v11);
            o0[ob + (2 * zp) * Mout + m]     += v00;
            o1[ob + (2 * zp) * Mout + m]     += v01;
            o0[ob + (2 * zp + 1) * Mout + m] += v10;
            o1[ob + (2 * zp + 1) * Mout + m] += v11;
        }
    }
}

__global__ __launch_bounds__(NTHREADS, 1)
void tp_o3_kernel(const float* __restrict__ x1, const float* __restrict__ x2,
                  const float* __restrict__ wgt, float* __restrict__ out) {
    extern __shared__ float sm[];
    float* sx1 = sm;
    float* sx2 = sx1 + SX_FLOATS;
    float* sB  = sx2 + SX_FLOATS;
    float* sW  = sB + SB_FLOATS;

    const int tid  = threadIdx.x;
    const int row0 = blockIdx.x * TILE;

    // stage input tiles (padded stride 833 -> conflict-free row-indexed reads)
    #pragma unroll 4
    for (int i = tid; i < TILE * FEAT; i += NTHREADS) {
        int r = i / FEAT, f = i - r * FEAT;
        sx1[r * SX_STRIDE + f] = x1[(size_t)(row0 + r) * FEAT + f];
        sx2[r * SX_STRIDE + f] = x2[(size_t)(row0 + r) * FEAT + f];
    }
    // (first __syncthreads inside each chunk loop orders the fill)

    process_path<0>(wgt, out, sx1, sx2, sB, sW, row0, tid);
    process_path<1>(wgt, out, sx1, sx2, sB, sW, row0, tid);
    process_path<2>(wgt, out, sx1, sx2, sB, sW, row0, tid);
    process_path<3>(wgt, out, sx1, sx2, sB, sW, row0, tid);
    process_path<4>(wgt, out, sx1, sx2, sB, sW, row0, tid);
    process_path<5>(wgt, out, sx1, sx2, sB, sW, row0, tid);
    process_path<6>(wgt, out, sx1, sx2, sB, sW, row0, tid);
    process_path<7>(wgt, out, sx1, sx2, sB, sW, row0, tid);
    process_path<8>(wgt, out, sx1, sx2, sB, sW, row0, tid);
    process_path<9>(wgt, out, sx1, sx2, sB, sW, row0, tid);
    process_path<10>(wgt, out, sx1, sx2, sB, sW, row0, tid);
    process_path<11>(wgt, out, sx1, sx2, sB, sW, row0, tid);
    process_path<12>(wgt, out, sx1, sx2, sB, sW, row0, tid);
    process_path<13>(wgt, out, sx1, sx2, sB, sW, row0, tid);
    process_path<14>(wgt, out, sx1, sx2, sB, sW, row0, tid);
}

extern "C" void kernel_launch(void* const* d_in, const int* in_sizes, int n_in,
                              void* d_out, int out_size) {
    const float* x1  = (const float*)d_in[0];
    const float* x2  = (const float*)d_in[1];
    const float* wgt = (const float*)d_in[2];
    float* out = (float*)d_out;

    cudaFuncSetAttribute(tp_o3_kernel, cudaFuncAttributeMaxDynamicSharedMemorySize, SMEM_BYTES);
    cudaMemsetAsync(d_out, 0, (size_t)out_size * sizeof(float), 0);
    tp_o3_kernel<<<NROWS / TILE, NTHREADS, SMEM_BYTES>>>(x1, x2, wgt, out);
}

// round 7
// speedup vs baseline: 1.6975x; 1.2237x over previous
#include <cuda_runtime.h>
#include <cstdint>

// ---------------------------------------------------------------------------
// PureCartesianTensorProductO3.
// R7: R5 skeleton (256 thr, 2 ss-groups with equal s_out, CHUNK=2) fixed:
//  - __launch_bounds__(256,1): lift reg cap (R5 spilled at 128 regs)
//  - sB relayout [m][rp][2k+parity]: LDS.128 feeds TWO k per load
//  - W in R4's conflict-free [k][Z] stride-34 layout
// ---------------------------------------------------------------------------

#define NROWS   8192
#define FEAT    832
#define SBLK    416
#define TILE    16
#define NTHREADS 256
#define CHUNK   2
#define KSLOTS  (CHUNK * 32)      // 64 k-slots per staged chunk

// path tables (compile-time)
__host__ __device__ constexpr int kP3[3]   = {1, 3, 9};
__host__ __device__ constexpr int kLOFF[3] = {0, 32, 128};
__host__ __device__ constexpr int kL1[15] = {0,0,0,1,1,1,1,1,1,2,2,2,2,2,2};
__host__ __device__ constexpr int kL2[15] = {0,1,2,0,1,1,1,2,2,0,1,1,2,2,2};
__host__ __device__ constexpr int kLO[15] = {0,1,2,1,2,0,1,1,2,2,1,2,2,0,1};
__host__ __device__ constexpr int kUE[15] = {0,0,0,0,0,0,1,0,1,0,0,1,0,0,1};

// SMEM carve (floats)
#define SX_STRIDE 832
#define SX_FLOATS (TILE * SX_STRIDE)           // 13312
// sB per group: [m][rp(8)][2k+(r&1), 128 floats] -> m-stride 1024, max Mout 9
#define SB_G      (9 * 1024)                   // 9216 per group
#define SW_STRIDE 34
#define SW_G      (KSLOTS * SW_STRIDE)         // 2176 per group
#define SMEM_FLOATS (2 * SX_FLOATS + 2 * SB_G + 2 * SW_G)   // 49408
#define SMEM_BYTES (SMEM_FLOATS * 4)           // 197632 B

typedef unsigned long long u64;

__device__ __forceinline__ u64 pk2(float x, float y) {
    u64 r; asm("mov.b64 %0, {%1, %2};" : "=l"(r) : "f"(x), "f"(y)); return r;
}
__device__ __forceinline__ void upk2(u64 v, float& x, float& y) {
    asm("mov.b64 {%0, %1}, %2;" : "=f"(x), "=f"(y) : "l"(v));
}
// packed 2x fp32 FMA (PTX-only on sm_103a)
__device__ __forceinline__ void ffma2(u64& d, u64 a, u64 b) {
    asm("fma.rn.f32x2 %0, %1, %2, %0;" : "+l"(d) : "l"(a), "l"(b));
}

__device__ __forceinline__ float dot3(const float* __restrict__ u, const float* __restrict__ v) {
    return fmaf(u[0], v[0], fmaf(u[1], v[1], u[2] * v[2]));
}
__device__ __forceinline__ void cross3(const float* __restrict__ u, const float* __restrict__ v,
                                       float* __restrict__ o) {
    o[0] = u[1] * v[2] - u[2] * v[1];
    o[1] = u[2] * v[0] - u[0] * v[2];
    o[2] = u[0] * v[1] - u[1] * v[0];
}

// Spatial contraction per path (verified against _path_eq; unchanged since R1 fix)
template <int P>
__device__ __forceinline__ void compute_B(const float* __restrict__ t1,
                                          const float* __restrict__ t2,
                                          float* __restrict__ B) {
    if constexpr (P == 0) {
        B[0] = t1[0] * t2[0];
    } else if constexpr (P == 1) {
        #pragma unroll
        for (int m = 0; m < 3; ++m) B[m] = t1[0] * t2[m];
    } else if constexpr (P == 2) {
        #pragma unroll
        for (int m = 0; m < 9; ++m) B[m] = t1[0] * t2[m];
    } else if constexpr (P == 3) {
        #pragma unroll
        for (int m = 0; m < 3; ++m) B[m] = t1[m] * t2[0];
    } else if constexpr (P == 4) {
        #pragma unroll
        for (int i = 0; i < 3; ++i)
            #pragma unroll
            for (int j = 0; j < 3; ++j) B[3 * i + j] = t1[i] * t2[j];
    } else if constexpr (P == 5) {
        B[0] = dot3(t1, t2);
    } else if constexpr (P == 6) {
        cross3(t1, t2, B);
    } else if constexpr (P == 7) {
        #pragma unroll
        for (int d = 0; d < 3; ++d) B[d] = dot3(t1, t2 + 3 * d);
    } else if constexpr (P == 8) {
        #pragma unroll
        for (int d = 0; d < 3; ++d) cross3(t1, t2 + 3 * d, B + 3 * d);
    } else if constexpr (P == 9) {
        #pragma unroll
        for (int m = 0; m < 9; ++m) B[m] = t1[m] * t2[0];
    } else if constexpr (P == 10) {
        #pragma unroll
        for (int c = 0; c < 3; ++c) B[c] = dot3(t1 + 3 * c, t2);
    } else if constexpr (P == 11) {
        #pragma unroll
        for (int c = 0; c < 3; ++c) cross3(t1 + 3 * c, t2, B + 3 * c);
    } else if constexpr (P == 12) {
        #pragma unroll
        for (int c = 0; c < 3; ++c)
            #pragma unroll
            for (int e = 0; e < 3; ++e) B[3 * c + e] = dot3(t1 + 3 * c, t2 + 3 * e);
    } else if constexpr (P == 13) {
        float s = 0.f;
        #pragma unroll
        for (int i = 0; i < 9; ++i) s = fmaf(t1[i], t2[i], s);
        B[0] = s;
    } else {  // P==14
        float M01 = dot3(t1 + 0, t2 + 3), M02 = dot3(t1 + 0, t2 + 6);
        float M10 = dot3(t1 + 3, t2 + 0), M12 = dot3(t1 + 3, t2 + 6);
        float M20 = dot3(t1 + 6, t2 + 0), M21 = dot3(t1 + 6, t2 + 3);
        B[0] = M12 - M21;
        B[1] = M20 - M02;
        B[2] = M01 - M10;
    }
}

template <int P>
__device__ __forceinline__ void process_path(const float* __restrict__ wgt,
                                             float* __restrict__ out,
                                             const float* __restrict__ sx1,
                                             const float* __restrict__ sx2,
                                             float* __restrict__ sB,   // group's buffer
                                             float* __restrict__ sW,   // group's buffer
                                             int row0, int wtid, int group) {
    constexpr int L1 = kL1[P], L2 = kL2[P], Lo = kLO[P], UE = kUE[P];
    constexpr int d1 = kP3[L1], d2 = kP3[L2], Mout = kP3[Lo];
    constexpr int O1 = kLOFF[L1], O2 = kLOFF[L2], Oo = kLOFF[Lo];

    const int zp = wtid & 15;   // Z-pair: Z = 2*zp, 2*zp+1
    const int rp = wtid >> 4;   // row-pair: rows 2*rp, 2*rp+1  (rp in [0,8))

    // group0 handles ss {0,3} (s_out = UE), group1 handles ss {1,2} (s_out = 1^UE)
    const int s_out = (group == 0) ? UE : (1 ^ UE);

    u64 acc0[Mout], acc1[Mout];
    #pragma unroll
    for (int m = 0; m < Mout; ++m) { acc0[m] = 0ull; acc1[m] = 0ull; }

    #pragma unroll 1
    for (int ssi = 0; ssi < 2; ++ssi) {
        const int ss = (group == 0) ? (ssi == 0 ? 0 : 3) : (ssi == 0 ? 1 : 2);
        const int s1 = ss >> 1, s2 = ss & 1;
        const float* wb = wgt + (size_t)(P * 4 + ss) * 32768;

        #pragma unroll 1
        for (int a0 = 0; a0 < 32; a0 += CHUNK) {
            __syncthreads();  // prior GEMM done reading sB/sW (also orders x fill)
            // ---- stage W slice: sW[k*34 + Z] = W[Z, a0*32 + k], k in [0,64)
            #pragma unroll
            for (int it = 0; it < 32 * KSLOTS / 128; ++it) {
                int i = wtid + it * 128;
                int Z = i >> 6, k = i & (KSLOTS - 1);
                sW[k * SW_STRIDE + Z] = wb[Z * 1024 + a0 * 32 + k];
            }
            // ---- stage B: 64 slots x 16 rows; layout [m][rp][2k + (r&1)]
            #pragma unroll
            for (int it = 0; it < KSLOTS * TILE / 128; ++it) {
                int e = wtid + it * 128;
                int k = e & (KSLOTS - 1), r = e >> 6;   // k slot-fast: conflict-lean x reads
                int ac = k >> 5, b = k & 31;
                const float* t1 = sx1 + r * SX_STRIDE + s1 * SBLK + O1 + (a0 + ac) * d1;
                const float* t2 = sx2 + r * SX_STRIDE + s2 * SBLK + O2 + b * d2;
                float Bm[Mout];
                compute_B<P>(t1, t2, Bm);
                float* d = sB + (r >> 1) * 128 + 2 * k + (r & 1);
                #pragma unroll
                for (int m = 0; m < Mout; ++m) d[m * 1024] = Bm[m];
            }
            __syncthreads();
            // ---- rank-64 update: 2 k per iteration via LDS.128 quads
            #pragma unroll 2
            for (int kk = 0; kk < KSLOTS / 2; ++kk) {
                // W for k=2kk and k=2kk+1 (each float2 over the Z-pair)
                float2 wa = *reinterpret_cast<const float2*>(sW + (2 * kk) * SW_STRIDE + 2 * zp);
                float2 wc = *reinterpret_cast<const float2*>(sW + (2 * kk + 1) * SW_STRIDE + 2 * zp);
                u64 wA0 = pk2(wa.x, wa.x);  // Z0, k
                u64 wB0 = pk2(wa.y, wa.y);  // Z1, k
                u64 wA1 = pk2(wc.x, wc.x);  // Z0, k+1
                u64 wB1 = pk2(wc.y, wc.y);  // Z1, k+1
                const float* bp = sB + rp * 128 + 4 * kk;
                #pragma unroll
                for (int m = 0; m < Mout; ++m) {
                    ulonglong2 q = *reinterpret_cast<const ulonglong2*>(bp + m * 1024);
                    ffma2(acc0[m], wA0, q.x);
                    ffma2(acc1[m], wB0, q.x);
                    ffma2(acc0[m], wA1, q.y);
                    ffma2(acc1[m], wB1, q.y);
                }
            }
        }
    }
    // ---- flush once per path per group (groups target disjoint s_out blocks)
    const int ob = s_out * SBLK + Oo;
    float* o0 = out + (size_t)(row0 + 2 * rp) * FEAT;
    float* o1 = o0 + FEAT;
    #pragma unroll
    for (int m = 0; m < Mout; ++m) {
        float v00, v01, v10, v11;
        upk2(acc0[m], v00, v01);
        upk2(acc1[m], v10, v11);
        o0[ob + (2 * zp) * Mout + m]     += v00;
        o1[ob + (2 * zp) * Mout + m]     += v01;
        o0[ob + (2 * zp + 1) * Mout + m] += v10;
        o1[ob + (2 * zp + 1) * Mout + m] += v11;
    }
}

__global__ __launch_bounds__(NTHREADS, 1)
void tp_o3_kernel(const float* __restrict__ x1, const float* __restrict__ x2,
                  const float* __restrict__ wgt, float* __restrict__ out) {
    extern __shared__ float sm[];
    float* sx1 = sm;
    float* sx2 = sx1 + SX_FLOATS;
    float* sBb = sx2 + SX_FLOATS;
    float* sWb = sBb + 2 * SB_G;

    const int tid   = threadIdx.x;
    const int group = tid >> 7;
    const int wtid  = tid & 127;
    const int row0  = blockIdx.x * TILE;

    float* sB = sBb + group * SB_G;
    float* sW = sWb + group * SW_G;

    // stage input tiles (contiguous float4 copy)
    {
        const float4* g1 = reinterpret_cast<const float4*>(x1 + (size_t)row0 * FEAT);
        const float4* g2 = reinterpret_cast<const float4*>(x2 + (size_t)row0 * FEAT);
        float4* s1v = reinterpret_cast<float4*>(sx1);
        float4* s2v = reinterpret_cast<float4*>(sx2);
        #pragma unroll 4
        for (int i = tid; i < TILE * FEAT / 4; i += NTHREADS) {
            s1v[i] = g1[i];
            s2v[i] = g2[i];
        }
    }
    // (first __syncthreads inside each chunk loop orders the fill)

    process_path<0>(wgt, out, sx1, sx2, sB, sW, row0, wtid, group);
    process_path<1>(wgt, out, sx1, sx2, sB, sW, row0, wtid, group);
    process_path<2>(wgt, out, sx1, sx2, sB, sW, row0, wtid, group);
    process_path<3>(wgt, out, sx1, sx2, sB, sW, row0, wtid, group);
    process_path<4>(wgt, out, sx1, sx2, sB, sW, row0, wtid, group);
    process_path<5>(wgt, out, sx1, sx2, sB, sW, row0, wtid, group);
    process_path<6>(wgt, out, sx1, sx2, sB, sW, row0, wtid, group);
    process_path<7>(wgt, out, sx1, sx2, sB, sW, row0, wtid, group);
    process_path<8>(wgt, out, sx1, sx2, sB, sW, row0, wtid, group);
    process_path<9>(wgt, out, sx1, sx2, sB, sW, row0, wtid, group);
    process_path<10>(wgt, out, sx1, sx2, sB, sW, row0, wtid, group);
    process_path<11>(wgt, out, sx1, sx2, sB, sW, row0, wtid, group);
    process_path<12>(wgt, out, sx1, sx2, sB, sW, row0, wtid, group);
    process_path<13>(wgt, out, sx1, sx2, sB, sW, row0, wtid, group);
    process_path<14>(wgt, out, sx1, sx2, sB, sW, row0, wtid, group);
}

extern "C" void kernel_launch(void* const* d_in, const int* in_sizes, int n_in,
                              void* d_out, int out_size) {
    const float* x1  = (const float*)d_in[0];
    const float* x2  = (const float*)d_in[1];
    const float* wgt = (const float*)d_in[2];
    float* out = (float*)d_out;

    cudaFuncSetAttribute(tp_o3_kernel, cudaFuncAttributeMaxDynamicSharedMemorySize, SMEM_BYTES);
    cudaMemsetAsync(d_out, 0, (size_t)out_size * sizeof(float), 0);
    tp_o3_kernel<<<NROWS / TILE, NTHREADS, SMEM_BYTES>>>(x1, x2, wgt, out);
}

// round 8
// speedup vs baseline: 1.7734x; 1.0447x over previous
#include <cuda_runtime.h>
#include <cstdint>

// ---------------------------------------------------------------------------
// PureCartesianTensorProductO3.
// R8: paths sharing (L1,L2) merged into 9 groups -> one staging + one GEMM
// pass per group (x re-reads halved, small paths fused into fma-dense loops).
// 256 thr = 2 ss-groups (g0: ss{0,3}, g1: ss{1,2}; disjoint s_out). CHUNK=1.
// ---------------------------------------------------------------------------

#define NROWS   8192
#define FEAT    832
#define SBLK    416
#define TILE    16
#define NTHREADS 256
#define KSLOTS  32

// path tables (compile-time)
__host__ __device__ constexpr int kP3[3]   = {1, 3, 9};
__host__ __device__ constexpr int kLOFF[3] = {0, 32, 128};
__host__ __device__ constexpr int kL1[15] = {0,0,0,1,1,1,1,1,1,2,2,2,2,2,2};
__host__ __device__ constexpr int kL2[15] = {0,1,2,0,1,1,1,2,2,0,1,1,2,2,2};
__host__ __device__ constexpr int kLO[15] = {0,1,2,1,2,0,1,1,2,2,1,2,2,0,1};
__host__ __device__ constexpr int kUE[15] = {0,0,0,0,0,0,1,0,1,0,0,1,0,0,1};

// SMEM carve (floats)
#define SX_STRIDE 832
#define SX_FLOATS (TILE * SX_STRIDE)           // 13312
// sB per group: [m(<=13)][rp(8)][2k+(r&1), 64 floats] -> m-stride 512
#define SB_G      (13 * 512)                   // 6656
// sW per group: [p(<=3)][k*34 + Z]  (1088 per path)
#define SW_G      (3 * 1088)                   // 3264
#define SMEM_FLOATS (2 * SX_FLOATS + 2 * SB_G + 2 * SW_G)   // 46464
#define SMEM_BYTES (SMEM_FLOATS * 4)           // 185856 B

typedef unsigned long long u64;

__device__ __forceinline__ u64 pk2(float x, float y) {
    u64 r; asm("mov.b64 %0, {%1, %2};" : "=l"(r) : "f"(x), "f"(y)); return r;
}
__device__ __forceinline__ void upk2(u64 v, float& x, float& y) {
    asm("mov.b64 {%0, %1}, %2;" : "=f"(x), "=f"(y) : "l"(v));
}
// packed 2x fp32 FMA (PTX-only on sm_103a)
__device__ __forceinline__ void ffma2(u64& d, u64 a, u64 b) {
    asm("fma.rn.f32x2 %0, %1, %2, %0;" : "+l"(d) : "l"(a), "l"(b));
}

__device__ __forceinline__ float dot3(const float* __restrict__ u, const float* __restrict__ v) {
    return fmaf(u[0], v[0], fmaf(u[1], v[1], u[2] * v[2]));
}
__device__ __forceinline__ void cross3(const float* __restrict__ u, const float* __restrict__ v,
                                       float* __restrict__ o) {
    o[0] = u[1] * v[2] - u[2] * v[1];
    o[1] = u[2] * v[0] - u[0] * v[2];
    o[2] = u[0] * v[1] - u[1] * v[0];
}

// Spatial contraction per path (verified against _path_eq; unchanged since R1 fix)
template <int P>
__device__ __forceinline__ void compute_B(const float* __restrict__ t1,
                                          const float* __restrict__ t2,
                                          float* __restrict__ B) {
    if constexpr (P == 0) {
        B[0] = t1[0] * t2[0];
    } else if constexpr (P == 1) {
        #pragma unroll
        for (int m = 0; m < 3; ++m) B[m] = t1[0] * t2[m];
    } else if constexpr (P == 2) {
        #pragma unroll
        for (int m = 0; m < 9; ++m) B[m] = t1[0] * t2[m];
    } else if constexpr (P == 3) {
        #pragma unroll
        for (int m = 0; m < 3; ++m) B[m] = t1[m] * t2[0];
    } else if constexpr (P == 4) {
        #pragma unroll
        for (int i = 0; i < 3; ++i)
            #pragma unroll
            for (int j = 0; j < 3; ++j) B[3 * i + j] = t1[i] * t2[j];
    } else if constexpr (P == 5) {
        B[0] = dot3(t1, t2);
    } else if constexpr (P == 6) {
        cross3(t1, t2, B);
    } else if constexpr (P == 7) {
        #pragma unroll
        for (int d = 0; d < 3; ++d) B[d] = dot3(t1, t2 + 3 * d);
    } else if constexpr (P == 8) {
        #pragma unroll
        for (int d = 0; d < 3; ++d) cross3(t1, t2 + 3 * d, B + 3 * d);
    } else if constexpr (P == 9) {
        #pragma unroll
        for (int m = 0; m < 9; ++m) B[m] = t1[m] * t2[0];
    } else if constexpr (P == 10) {
        #pragma unroll
        for (int c = 0; c < 3; ++c) B[c] = dot3(t1 + 3 * c, t2);
    } else if constexpr (P == 11) {
        #pragma unroll
        for (int c = 0; c < 3; ++c) cross3(t1 + 3 * c, t2, B + 3 * c);
    } else if constexpr (P == 12) {
        #pragma unroll
        for (int c = 0; c < 3; ++c)
            #pragma unroll
            for (int e = 0; e < 3; ++e) B[3 * c + e] = dot3(t1 + 3 * c, t2 + 3 * e);
    } else if constexpr (P == 13) {
        float s = 0.f;
        #pragma unroll
        for (int i = 0; i < 9; ++i) s = fmaf(t1[i], t2[i], s);
        B[0] = s;
    } else {  // P==14
        float M01 = dot3(t1 + 0, t2 + 3), M02 = dot3(t1 + 0, t2 + 6);
        float M10 = dot3(t1 + 3, t2 + 0), M12 = dot3(t1 + 3, t2 + 6);
        float M20 = dot3(t1 + 6, t2 + 0), M21 = dot3(t1 + 6, t2 + 3);
        B[0] = M12 - M21;
        B[1] = M20 - M02;
        B[2] = M01 - M10;
    }
}

// Merged processing for up to 3 paths sharing (L1,L2). PB/PC = -1 if absent.
template <int PA, int PB, int PC>
__device__ __forceinline__ void process_group(const float* __restrict__ wgt,
                                              float* __restrict__ out,
                                              const float* __restrict__ sx1,
                                              const float* __restrict__ sx2,
                                              float* __restrict__ sB,
                                              float* __restrict__ sW,
                                              int row0, int wtid, int group) {
    constexpr int NP = 1 + (PB >= 0 ? 1 : 0) + (PC >= 0 ? 1 : 0);
    constexpr int L1 = kL1[PA], L2 = kL2[PA];
    constexpr int d1 = kP3[L1], d2 = kP3[L2];
    constexpr int O1 = kLOFF[L1], O2 = kLOFF[L2];
    constexpr int MA = kP3[kLO[PA]];
    constexpr int MB = (PB >= 0) ? kP3[kLO[PB >= 0 ? PB : 0]] : 0;
    constexpr int MC = (PC >= 0) ? kP3[kLO[PC >= 0 ? PC : 0]] : 0;
    constexpr int MT = MA + MB + MC;

    const int zp = wtid & 15;   // Z-pair: Z = 2*zp, 2*zp+1
    const int rp = wtid >> 4;   // row-pair: rows 2*rp, 2*rp+1

    u64 acc0[MT], acc1[MT];
    #pragma unroll
    for (int m = 0; m < MT; ++m) { acc0[m] = 0ull; acc1[m] = 0ull; }

    #pragma unroll 1
    for (int ssi = 0; ssi < 2; ++ssi) {
        const int ss = (group == 0) ? (ssi == 0 ? 0 : 3) : (ssi == 0 ? 1 : 2);
        const int s1 = ss >> 1, s2 = ss & 1;

        #pragma unroll 1
        for (int a0 = 0; a0 < 32; ++a0) {
            __syncthreads();  // prior GEMM done reading sB/sW (also orders x fill)
            // ---- stage W: NP paths x 32 Z x 32 k  (coalesced gmem reads)
            #pragma unroll
            for (int it = 0; it < NP * 8; ++it) {
                int i = wtid + it * 128;
                int p = i >> 10, z = (i >> 5) & 31, k = i & 31;
                int pidx = (p == 0) ? PA : ((p == 1) ? PB : PC);
                sW[p * 1088 + k * 34 + z] =
                    wgt[(size_t)(pidx * 4 + ss) * 32768 + z * 1024 + a0 * 32 + k];
            }
            // ---- stage B: 32 k x 16 rows; one t1/t2 read serves all NP paths
            #pragma unroll
            for (int it = 0; it < 4; ++it) {
                int e = wtid + it * 128;
                int k = e & 31, r = e >> 5;   // k = lane -> t1 broadcast, t2 stride-d2
                const float* t1 = sx1 + r * SX_STRIDE + s1 * SBLK + O1 + a0 * d1;
                const float* t2 = sx2 + r * SX_STRIDE + s2 * SBLK + O2 + k * d2;
                float Bm[MT];
                compute_B<PA>(t1, t2, Bm);
                if constexpr (PB >= 0) compute_B<PB>(t1, t2, Bm + MA);
                if constexpr (PC >= 0) compute_B<PC>(t1, t2, Bm + MA + MB);
                float* d = sB + (r >> 1) * 64 + 2 * k + (r & 1);
                #pragma unroll
                for (int m = 0; m < MT; ++m) d[m * 512] = Bm[m];
            }
            __syncthreads();
            // ---- rank-32 update: 2 k per iteration, all MT outputs together
            #pragma unroll 2
            for (int kk = 0; kk < KSLOTS / 2; ++kk) {
                u64 wA0[NP], wB0[NP], wA1[NP], wB1[NP];
                #pragma unroll
                for (int p = 0; p < NP; ++p) {
                    float2 wa = *reinterpret_cast<const float2*>(
                        sW + p * 1088 + (2 * kk) * 34 + 2 * zp);
                    float2 wc = *reinterpret_cast<const float2*>(
                        sW + p * 1088 + (2 * kk + 1) * 34 + 2 * zp);
                    wA0[p] = pk2(wa.x, wa.x);
                    wB0[p] = pk2(wa.y, wa.y);
                    wA1[p] = pk2(wc.x, wc.x);
                    wB1[p] = pk2(wc.y, wc.y);
                }
                const float* bp = sB + rp * 64 + 4 * kk;
                #pragma unroll
                for (int m = 0; m < MT; ++m) {
                    const int p = (m < MA) ? 0 : ((m < MA + MB) ? 1 : 2);
                    ulonglong2 q = *reinterpret_cast<const ulonglong2*>(bp + m * 512);
                    ffma2(acc0[m], wA0[p], q.x);
                    ffma2(acc1[m], wB0[p], q.x);
                    ffma2(acc0[m], wA1[p], q.y);
                    ffma2(acc1[m], wB1[p], q.y);
                }
            }
        }
    }
    // ---- flush: per-m path properties constant-fold after unroll
    float* o0 = out + (size_t)(row0 + 2 * rp) * FEAT;
    float* o1 = o0 + FEAT;
    #pragma unroll
    for (int m = 0; m < MT; ++m) {
        const int p   = (m < MA) ? 0 : ((m < MA + MB) ? 1 : 2);
        const int P   = (p == 0) ? PA : ((p == 1) ? PB : PC);
        const int Lo  = kLO[P], UE = kUE[P];
        const int Mo  = kP3[Lo], Oo = kLOFF[Lo];
        const int mm  = m - ((p == 0) ? 0 : ((p == 1) ? MA : MA + MB));
        const int s_out = (group == 0) ? UE : (1 ^ UE);
        const int ob  = s_out * SBLK + Oo;
        float v00, v01, v10, v11;
        upk2(acc0[m], v00, v01);
        upk2(acc1[m], v10, v11);
        o0[ob + (2 * zp) * Mo + mm]     += v00;
        o1[ob + (2 * zp) * Mo + mm]     += v01;
        o0[ob + (2 * zp + 1) * Mo + mm] += v10;
        o1[ob + (2 * zp + 1) * Mo + mm] += v11;
    }
}

__global__ __launch_bounds__(NTHREADS, 1)
void tp_o3_kernel(const float* __restrict__ x1, const float* __restrict__ x2,
                  const float* __restrict__ wgt, float* __restrict__ out) {
    extern __shared__ float sm[];
    float* sx1 = sm;
    float* sx2 = sx1 + SX_FLOATS;
    float* sBb = sx2 + SX_FLOATS;
    float* sWb = sBb + 2 * SB_G;

    const int tid   = threadIdx.x;
    const int group = tid >> 7;
    const int wtid  = tid & 127;
    const int row0  = blockIdx.x * TILE;

    float* sB = sBb + group * SB_G;
    float* sW = sWb + group * SW_G;

    // stage input tiles (contiguous float4 copy)
    {
        const float4* g1 = reinterpret_cast<const float4*>(x1 + (size_t)row0 * FEAT);
        const float4* g2 = reinterpret_cast<const float4*>(x2 + (size_t)row0 * FEAT);
        float4* s1v = reinterpret_cast<float4*>(sx1);
        float4* s2v = reinterpret_cast<float4*>(sx2);
        #pragma unroll 4
        for (int i = tid; i < TILE * FEAT / 4; i += NTHREADS) {
            s1v[i] = g1[i];
            s2v[i] = g2[i];
        }
    }
    // (first __syncthreads inside each group's chunk loop orders the fill)

    process_group< 0, -1, -1>(wgt, out, sx1, sx2, sB, sW, row0, wtid, group);  // (0,0)
    process_group< 1, -1, -1>(wgt, out, sx1, sx2, sB, sW, row0, wtid, group);  // (0,1)
    process_group< 2, -1, -1>(wgt, out, sx1, sx2, sB, sW, row0, wtid, group);  // (0,2)
    process_group< 3, -1, -1>(wgt, out, sx1, sx2, sB, sW, row0, wtid, group);  // (1,0)
    process_group< 4,  5,  6>(wgt, out, sx1, sx2, sB, sW, row0, wtid, group);  // (1,1)
    process_group< 7,  8, -1>(wgt, out, sx1, sx2, sB, sW, row0, wtid, group);  // (1,2)
    process_group< 9, -1, -1>(wgt, out, sx1, sx2, sB, sW, row0, wtid, group);  // (2,0)
    process_group<10, 11, -1>(wgt, out, sx1, sx2, sB, sW, row0, wtid, group);  // (2,1)
    process_group<12, 13, 14>(wgt, out, sx1, sx2, sB, sW, row0, wtid, group);  // (2,2)
}

extern "C" void kernel_launch(void* const* d_in, const int* in_sizes, int n_in,
                              void* d_out, int out_size) {
    const float* x1  = (const float*)d_in[0];
    const float* x2  = (const float*)d_in[1];
    const float* wgt = (const float*)d_in[2];
    float* out = (float*)d_out;

    cudaFuncSetAttribute(tp_o3_kernel, cudaFuncAttributeMaxDynamicSharedMemorySize, SMEM_BYTES);
    cudaMemsetAsync(d_out, 0, (size_t)out_size * sizeof(float), 0);
    tp_o3_kernel<<<NROWS / TILE, NTHREADS, SMEM_BYTES>>>(x1, x2, wgt, out);
}